// round 8
// baseline (speedup 1.0000x reference)
#include <cuda_runtime.h>
#include <cuda_fp16.h>

#define NN 50000
#define EE 800000
#define E2 850000      // EE + NN self loops
#define HC 256
#define HEADS 4
#define HID 64
#define OUTD 86
#define SCAN_BLK 256
#define NBLK_SCAN ((NN + SCAN_BLK - 1) / SCAN_BLK)   // 196

// GEMM tiling: 128x128 block tile (2 heads), 8 warps of 32x64
#define BM 128
#define BNT 128
#define BK 32
#define ASTRIDE 36
#define BSTRIDE 136
#define ASZ (BM * ASTRIDE)
#define BSZ (BK * BSTRIDE)
#define GEMM_SMEM ((2 * ASZ + 2 * BSZ) * 4)

// ---- scratch (device globals: allocation-free) ----
__device__ __half g_h[NN * HC];         // post-GEMM features, fp16
__device__ float g_agg[NN * HC];
__device__ float g_as[NN * HEADS];
__device__ float g_ad[NN * HEADS];
__device__ float g_y[NN * HID];
__device__ float g_stats[2 * HC];
__device__ float g_scale[HC];
__device__ float g_shift[HC];
__device__ int   g_src[E2];
__device__ int   g_dst[E2];
__device__ int   g_rank[E2];
__device__ int   g_deg[NN];
__device__ int   g_off[NN + 1];
__device__ int   g_bsum[SCAN_BLK];
__device__ int   g_boff[SCAN_BLK];
__device__ int   g_csr[E2];
__device__ int   g_is64;

// ---------------- dtype probe + zero degree array (single block) ----------------
__global__ void detect_dtype(const int* __restrict__ ei32) {
    __shared__ int any;
    int t = threadIdx.x;
    if (t == 0) any = 0;
    __syncthreads();
    if (ei32[2 * t + 1] != 0) any = 1;
    for (int i = t; i < NN; i += 256) g_deg[i] = 0;
    __syncthreads();
    if (t == 0) g_is64 = !any;
}

// ---------------- normalize edge index + self loops + degree histogram ----------------
__global__ void convert_hist(const void* __restrict__ eiv) {
    int e = blockIdx.x * blockDim.x + threadIdx.x;
    if (e >= E2) return;
    int s, d;
    if (e >= EE) {
        s = d = e - EE;
    } else if (g_is64) {
        const long long* p = (const long long*)eiv;
        s = (int)p[e];
        d = (int)p[EE + e];
    } else {
        const int* p = (const int*)eiv;
        s = p[e];
        d = p[EE + e];
    }
    g_src[e] = s;
    g_dst[e] = d;
    g_rank[e] = atomicAdd(&g_deg[d], 1);
}

__global__ void scan1() {
    __shared__ int sh[SCAN_BLK];
    int t = threadIdx.x, b = blockIdx.x;
    int idx = b * SCAN_BLK + t;
    sh[t] = (idx < NN) ? g_deg[idx] : 0;
    __syncthreads();
    for (int o = 128; o > 0; o >>= 1) {
        if (t < o) sh[t] += sh[t + o];
        __syncthreads();
    }
    if (t == 0) g_bsum[b] = sh[0];
}

__global__ void scan2() {
    __shared__ int sh[SCAN_BLK];
    int t = threadIdx.x;
    sh[t] = (t < NBLK_SCAN) ? g_bsum[t] : 0;
    __syncthreads();
    int v = sh[t];
    for (int o = 1; o < SCAN_BLK; o <<= 1) {
        int u = (t >= o) ? sh[t - o] : 0;
        __syncthreads();
        sh[t] += u;
        __syncthreads();
    }
    g_boff[t] = sh[t] - v;
    if (t == 0) g_off[NN] = E2;
}

__global__ void scan3() {
    __shared__ int sh[SCAN_BLK];
    int t = threadIdx.x, b = blockIdx.x;
    int idx = b * SCAN_BLK + t;
    int v = (idx < NN) ? g_deg[idx] : 0;
    sh[t] = v;
    __syncthreads();
    for (int o = 1; o < SCAN_BLK; o <<= 1) {
        int u = (t >= o) ? sh[t - o] : 0;
        __syncthreads();
        sh[t] += u;
        __syncthreads();
    }
    if (idx < NN) g_off[idx] = g_boff[b] + sh[t] - v;
}

__global__ void scatter_csr() {
    int e = blockIdx.x * blockDim.x + threadIdx.x;
    if (e >= E2) return;
    g_csr[g_off[g_dst[e]] + g_rank[e]] = g_src[e];
}

// ---------------- TF32 GEMM 128x128 + fused BN/PReLU pre-op + attn epilogue ----------------
__device__ __forceinline__ unsigned f2tf(float x) {
    unsigned r;
    asm("cvt.rna.tf32.f32 %0, %1;" : "=r"(r) : "f"(x));
    return r;
}

__global__ __launch_bounds__(256) void gemm_tf32(
        const float* __restrict__ A, const float* __restrict__ B,
        __half* __restrict__ C, const float* __restrict__ attS,
        const float* __restrict__ attD, int M,
        const float* __restrict__ scale, const float* __restrict__ shift,
        const float* __restrict__ pw) {
    extern __shared__ float sm[];
    float* sA = sm;
    float* sB = sm + 2 * ASZ;
    const int K = 256;
    int tid = threadIdx.x, lane = tid & 31, warp = tid >> 5;
    int wm = warp >> 1, wn = warp & 1;   // 4x2 warps, 32x64 per warp
    int g = lane >> 2, tg = lane & 3;
    int rowBase = blockIdx.y * BM;
    int colBase = blockIdx.x * BNT;
    int head = blockIdx.x * 2 + wn;      // each warp owns a full head
    float w = scale ? pw[0] : 0.f;

    float acc[2][8][4];
    #pragma unroll
    for (int mt = 0; mt < 2; mt++)
        #pragma unroll
        for (int nt = 0; nt < 8; nt++)
            #pragma unroll
            for (int i = 0; i < 4; i++) acc[mt][nt][i] = 0.f;

    float4 av[4], bv[4];
    auto loadA = [&](int k0) {
        #pragma unroll
        for (int i = 0; i < 4; i++) {
            int F = tid + i * 256;
            int r = rowBase + (F >> 3);
            int c = (F & 7) * 4;
            if (r < M) {
                float4 v = *(const float4*)(A + (long)r * K + k0 + c);
                if (scale) {
                    float4 sc = *(const float4*)(scale + k0 + c);
                    float4 sh = *(const float4*)(shift + k0 + c);
                    v.x = fmaf(v.x, sc.x, sh.x); v.x = (v.x >= 0.f) ? v.x : w * v.x;
                    v.y = fmaf(v.y, sc.y, sh.y); v.y = (v.y >= 0.f) ? v.y : w * v.y;
                    v.z = fmaf(v.z, sc.z, sh.z); v.z = (v.z >= 0.f) ? v.z : w * v.z;
                    v.w = fmaf(v.w, sc.w, sh.w); v.w = (v.w >= 0.f) ? v.w : w * v.w;
                }
                av[i] = v;
            } else {
                av[i] = make_float4(0.f, 0.f, 0.f, 0.f);
            }
        }
        #pragma unroll
        for (int i = 0; i < 4; i++) {
            int F = tid + i * 256;
            int r = k0 + (F >> 5);
            int c = colBase + (F & 31) * 4;
            bv[i] = *(const float4*)(B + (long)r * HC + c);
        }
    };
    auto storeT = [&](int buf) {
        float* pA = sA + buf * ASZ;
        #pragma unroll
        for (int i = 0; i < 4; i++) {
            int F = tid + i * 256;
            int r = F >> 3, c = (F & 7) * 4;
            float4 v;
            v.x = __uint_as_float(f2tf(av[i].x));
            v.y = __uint_as_float(f2tf(av[i].y));
            v.z = __uint_as_float(f2tf(av[i].z));
            v.w = __uint_as_float(f2tf(av[i].w));
            *(float4*)(pA + r * ASTRIDE + c) = v;
        }
        float* pB = sB + buf * BSZ;
        #pragma unroll
        for (int i = 0; i < 4; i++) {
            int F = tid + i * 256;
            int r = F >> 5, c = (F & 31) * 4;
            float4 v;
            v.x = __uint_as_float(f2tf(bv[i].x));
            v.y = __uint_as_float(f2tf(bv[i].y));
            v.z = __uint_as_float(f2tf(bv[i].z));
            v.w = __uint_as_float(f2tf(bv[i].w));
            *(float4*)(pB + r * BSTRIDE + c) = v;
        }
    };

    loadA(0);
    storeT(0);
    __syncthreads();

    const int iters = K / BK;
    for (int it = 0; it < iters; it++) {
        int buf = it & 1;
        if (it + 1 < iters) loadA((it + 1) * BK);
        const float* pA = sA + buf * ASZ;
        const float* pB = sB + buf * BSZ;
        #pragma unroll
        for (int ks = 0; ks < 4; ks++) {
            int k = ks * 8;
            unsigned a[2][4], b[8][2];
            #pragma unroll
            for (int mt = 0; mt < 2; mt++) {
                int r0 = wm * 32 + mt * 16;
                a[mt][0] = __float_as_uint(pA[(r0 + g) * ASTRIDE + k + tg]);
                a[mt][1] = __float_as_uint(pA[(r0 + g + 8) * ASTRIDE + k + tg]);
                a[mt][2] = __float_as_uint(pA[(r0 + g) * ASTRIDE + k + tg + 4]);
                a[mt][3] = __float_as_uint(pA[(r0 + g + 8) * ASTRIDE + k + tg + 4]);
            }
            #pragma unroll
            for (int nt = 0; nt < 8; nt++) {
                int c0 = wn * 64 + nt * 8;
                b[nt][0] = __float_as_uint(pB[(k + tg) * BSTRIDE + c0 + g]);
                b[nt][1] = __float_as_uint(pB[(k + tg + 4) * BSTRIDE + c0 + g]);
            }
            #pragma unroll
            for (int mt = 0; mt < 2; mt++)
                #pragma unroll
                for (int nt = 0; nt < 8; nt++) {
                    asm volatile(
                        "mma.sync.aligned.m16n8k8.row.col.f32.tf32.tf32.f32 "
                        "{%0,%1,%2,%3}, {%4,%5,%6,%7}, {%8,%9}, {%0,%1,%2,%3};"
                        : "+f"(acc[mt][nt][0]), "+f"(acc[mt][nt][1]),
                          "+f"(acc[mt][nt][2]), "+f"(acc[mt][nt][3])
                        : "r"(a[mt][0]), "r"(a[mt][1]), "r"(a[mt][2]), "r"(a[mt][3]),
                          "r"(b[nt][0]), "r"(b[nt][1]));
                }
        }
        if (it + 1 < iters) storeT(buf ^ 1);
        __syncthreads();
    }

    // ---- C store (fp16) ----
    #pragma unroll
    for (int mt = 0; mt < 2; mt++) {
        int r = rowBase + wm * 32 + mt * 16 + g;
        #pragma unroll
        for (int nt = 0; nt < 8; nt++) {
            int c = colBase + wn * 64 + nt * 8 + tg * 2;
            if (r < M)
                *(__half2*)(C + (long)r * HC + c) =
                    __floats2half2_rn(acc[mt][nt][0], acc[mt][nt][1]);
            if (r + 8 < M)
                *(__half2*)(C + (long)(r + 8) * HC + c) =
                    __floats2half2_rn(acc[mt][nt][2], acc[mt][nt][3]);
        }
    }

    // ---- fused attention scores: warp-local (each warp owns one head) ----
    float ps0[2] = {0.f, 0.f}, ps1[2] = {0.f, 0.f};
    float pd0[2] = {0.f, 0.f}, pd1[2] = {0.f, 0.f};
    #pragma unroll
    for (int nt = 0; nt < 8; nt++) {
        int lc = nt * 8 + tg * 2;         // column within head
        float s0 = attS[head * HID + lc], s1 = attS[head * HID + lc + 1];
        float d0 = attD[head * HID + lc], d1 = attD[head * HID + lc + 1];
        #pragma unroll
        for (int mt = 0; mt < 2; mt++) {
            ps0[mt] += acc[mt][nt][0] * s0 + acc[mt][nt][1] * s1;
            ps1[mt] += acc[mt][nt][2] * s0 + acc[mt][nt][3] * s1;
            pd0[mt] += acc[mt][nt][0] * d0 + acc[mt][nt][1] * d1;
            pd1[mt] += acc[mt][nt][2] * d0 + acc[mt][nt][3] * d1;
        }
    }
    #pragma unroll
    for (int o = 1; o <= 2; o <<= 1) {
        #pragma unroll
        for (int mt = 0; mt < 2; mt++) {
            ps0[mt] += __shfl_xor_sync(0xffffffffu, ps0[mt], o);
            ps1[mt] += __shfl_xor_sync(0xffffffffu, ps1[mt], o);
            pd0[mt] += __shfl_xor_sync(0xffffffffu, pd0[mt], o);
            pd1[mt] += __shfl_xor_sync(0xffffffffu, pd1[mt], o);
        }
    }
    if (tg == 0) {
        #pragma unroll
        for (int mt = 0; mt < 2; mt++) {
            int r = rowBase + wm * 32 + mt * 16 + g;
            if (r < M) {
                g_as[r * HEADS + head] = ps0[mt];
                g_ad[r * HEADS + head] = pd0[mt];
            }
            if (r + 8 < M) {
                g_as[(r + 8) * HEADS + head] = ps1[mt];
                g_ad[(r + 8) * HEADS + head] = pd1[mt];
            }
        }
    }
}

// ---------------- CSR aggregation: SINGLE PASS, warp per dst node ----------------
__device__ __forceinline__ void fma8(float* a, float al, uint4 v) {
    float2 f0 = __half22float2(*(__half2*)&v.x);
    float2 f1 = __half22float2(*(__half2*)&v.y);
    float2 f2 = __half22float2(*(__half2*)&v.z);
    float2 f3 = __half22float2(*(__half2*)&v.w);
    a[0] = fmaf(al, f0.x, a[0]); a[1] = fmaf(al, f0.y, a[1]);
    a[2] = fmaf(al, f1.x, a[2]); a[3] = fmaf(al, f1.y, a[3]);
    a[4] = fmaf(al, f2.x, a[4]); a[5] = fmaf(al, f2.y, a[5]);
    a[6] = fmaf(al, f3.x, a[6]); a[7] = fmaf(al, f3.y, a[7]);
}

__global__ void agg_csr(const __half* __restrict__ hsrc, float* __restrict__ outp,
                        int meanHeads) {
    // fold BN-stats zeroing into this kernel (completes before bn_stats launches)
    if (blockIdx.x == 0) {
        g_stats[threadIdx.x] = 0.f;
        g_stats[threadIdx.x + 256] = 0.f;
    }
    int d = (blockIdx.x * blockDim.x + threadIdx.x) >> 5;
    int lane = threadIdx.x & 31;
    if (d >= NN) return;
    int start = g_off[d], end = g_off[d + 1];
    int hh = lane >> 3;                 // lane covers channels [lane*8, lane*8+8)
    float dvh = g_ad[d * HEADS + hh];
    // single pass: accumulate unnormalized weighted features + denominator
    float den = 0.f;
    float a[8] = {0.f, 0.f, 0.f, 0.f, 0.f, 0.f, 0.f, 0.f};
    int e = start;
    for (; e + 4 <= end; e += 4) {
        int s0 = g_csr[e],     s1 = g_csr[e + 1];
        int s2 = g_csr[e + 2], s3 = g_csr[e + 3];
        float l0 = g_as[s0 * HEADS + hh] + dvh;
        float l1 = g_as[s1 * HEADS + hh] + dvh;
        float l2 = g_as[s2 * HEADS + hh] + dvh;
        float l3 = g_as[s3 * HEADS + hh] + dvh;
        uint4 v0 = *((const uint4*)(hsrc + (long)s0 * HC) + lane);
        uint4 v1 = *((const uint4*)(hsrc + (long)s1 * HC) + lane);
        uint4 v2 = *((const uint4*)(hsrc + (long)s2 * HC) + lane);
        uint4 v3 = *((const uint4*)(hsrc + (long)s3 * HC) + lane);
        l0 = fmaxf(l0, 0.2f * l0); float w0 = __expf(l0);
        l1 = fmaxf(l1, 0.2f * l1); float w1 = __expf(l1);
        l2 = fmaxf(l2, 0.2f * l2); float w2 = __expf(l2);
        l3 = fmaxf(l3, 0.2f * l3); float w3 = __expf(l3);
        den += w0 + w1 + w2 + w3;
        fma8(a, w0, v0);
        fma8(a, w1, v1);
        fma8(a, w2, v2);
        fma8(a, w3, v3);
    }
    for (; e < end; e++) {
        int s0 = g_csr[e];
        float l0 = g_as[s0 * HEADS + hh] + dvh;
        uint4 v0 = *((const uint4*)(hsrc + (long)s0 * HC) + lane);
        l0 = fmaxf(l0, 0.2f * l0);
        float w0 = __expf(l0);
        den += w0;
        fma8(a, w0, v0);
    }
    float invh = 1.f / (den + 1e-16f);
    #pragma unroll
    for (int j = 0; j < 8; j++) a[j] *= invh;
    if (!meanHeads) {
        float4* op = (float4*)(outp + (long)d * HC) + lane * 2;
        op[0] = make_float4(a[0], a[1], a[2], a[3]);
        op[1] = make_float4(a[4], a[5], a[6], a[7]);
    } else {
        // mean over heads: lanes L, L^8, L^16, L^24 hold same local channels
        #pragma unroll
        for (int j = 0; j < 8; j++) {
            a[j] += __shfl_xor_sync(0xffffffffu, a[j], 8);
            a[j] += __shfl_xor_sync(0xffffffffu, a[j], 16);
        }
        if (lane < 8) {
            float4* op = (float4*)(outp + (long)d * HID) + lane * 2;
            op[0] = make_float4(0.25f * a[0], 0.25f * a[1], 0.25f * a[2], 0.25f * a[3]);
            op[1] = make_float4(0.25f * a[4], 0.25f * a[5], 0.25f * a[6], 0.25f * a[7]);
        }
    }
}

__global__ void bn_stats(const float* __restrict__ x, int N, int C) {
    int tid = threadIdx.x;
    int c = tid % C;
    int g = tid / C;
    int G = blockDim.x / C;
    int rows_per_block = (N + gridDim.x - 1) / gridDim.x;
    int r0 = blockIdx.x * rows_per_block;
    int r1 = min(N, r0 + rows_per_block);
    float s = 0.f, q = 0.f;
    for (int r = r0 + g; r < r1; r += G) {
        float v = x[(long)r * C + c];
        s += v;
        q += v * v;
    }
    __shared__ float sh[512];
    sh[tid] = s;
    sh[256 + tid] = q;
    __syncthreads();
    if (g == 0) {
        for (int gg = 1; gg < G; gg++) {
            s += sh[gg * C + c];
            q += sh[256 + gg * C + c];
        }
        atomicAdd(&g_stats[c], s);
        atomicAdd(&g_stats[C + c], q);
    }
}

__global__ void bn_finalize(const float* __restrict__ gamma,
                            const float* __restrict__ beta, int N, int C) {
    int c = threadIdx.x;
    if (c >= C) return;
    float invN = 1.f / (float)N;
    float mean = g_stats[c] * invN;
    float var = g_stats[C + c] * invN - mean * mean;
    float sc = gamma[c] * rsqrtf(var + 1e-5f);
    g_scale[c] = sc;
    g_shift[c] = beta[c] - mean * sc;
}

__global__ void bn_apply_elu(float* __restrict__ x, const float* __restrict__ gamma,
                             const float* __restrict__ beta, int N, int C) {
    int i = blockIdx.x * blockDim.x + threadIdx.x;
    if (i >= N * C) return;
    int c = i % C;
    float invN = 1.f / (float)N;
    float mean = g_stats[c] * invN;
    float var = g_stats[C + c] * invN - mean * mean;
    float inv = rsqrtf(var + 1e-5f);
    float v = (x[i] - mean) * inv * gamma[c] + beta[c];
    v = (v > 0.f) ? v : expm1f(v);
    x[i] = v;
}

__global__ void fc_out(const float* __restrict__ W, const float* __restrict__ b,
                       float* __restrict__ out) {
    __shared__ float sW[HID * OUTD];
    for (int l = threadIdx.x; l < HID * OUTD; l += blockDim.x)
        sW[l] = W[l];
    __syncthreads();
    int i = blockIdx.x * blockDim.x + threadIdx.x;
    if (i >= NN * OUTD) return;
    int n = i / OUTD, o = i - n * OUTD;
    const float4* y4 = (const float4*)(g_y + (long)n * HID);
    float acc = b[o];
    #pragma unroll
    for (int k = 0; k < 16; k++) {
        float4 v = y4[k];
        acc += v.x * sW[(4 * k) * OUTD + o];
        acc += v.y * sW[(4 * k + 1) * OUTD + o];
        acc += v.z * sW[(4 * k + 2) * OUTD + o];
        acc += v.w * sW[(4 * k + 3) * OUTD + o];
    }
    out[i] = acc;
}

extern "C" void kernel_launch(void* const* d_in, const int* in_sizes, int n_in,
                              void* d_out, int out_size) {
    const float* x   = (const float*)d_in[0];
    const void*  ei  = d_in[1];
    const float* W1  = (const float*)d_in[2];
    const float* as1 = (const float*)d_in[3];
    const float* ad1 = (const float*)d_in[4];
    const float* W2  = (const float*)d_in[6];
    const float* as2 = (const float*)d_in[7];
    const float* ad2 = (const float*)d_in[8];
    const float* g1  = (const float*)d_in[10];
    const float* be1 = (const float*)d_in[11];
    const float* g2  = (const float*)d_in[12];
    const float* be2 = (const float*)d_in[13];
    const float* pw  = (const float*)d_in[14];
    const float* fcW = (const float*)d_in[15];
    const float* fcb = (const float*)d_in[16];
    float* out = (float*)d_out;

    __half* p_h;
    float *p_agg, *p_y, *p_scale, *p_shift;
    cudaGetSymbolAddress((void**)&p_h, g_h);
    cudaGetSymbolAddress((void**)&p_agg, g_agg);
    cudaGetSymbolAddress((void**)&p_y, g_y);
    cudaGetSymbolAddress((void**)&p_scale, g_scale);
    cudaGetSymbolAddress((void**)&p_shift, g_shift);

    static int smem_set = 0;
    if (!smem_set) {
        cudaFuncSetAttribute(gemm_tf32, cudaFuncAttributeMaxDynamicSharedMemorySize,
                             GEMM_SMEM);
        smem_set = 1;
    }

    dim3 gemmGrid(HC / BNT, (NN + BM - 1) / BM);   // (2, 391)
    int edgeBlocks = (E2 + 255) / 256;
    int aggBlocks  = (NN * 32 + 255) / 256;

    // ---- CSR build ----
    detect_dtype<<<1, 256>>>((const int*)ei);
    convert_hist<<<edgeBlocks, 256>>>(ei);
    scan1<<<NBLK_SCAN, SCAN_BLK>>>();
    scan2<<<1, SCAN_BLK>>>();
    scan3<<<NBLK_SCAN, SCAN_BLK>>>();
    scatter_csr<<<edgeBlocks, 256>>>();

    // ---- layer 1 ----
    gemm_tf32<<<gemmGrid, 256, GEMM_SMEM>>>(x, W1, p_h, as1, ad1, NN,
                                            nullptr, nullptr, nullptr);
    agg_csr<<<aggBlocks, 256>>>(p_h, p_agg, 0);
    bn_stats<<<512, 256>>>(p_agg, NN, HC);
    bn_finalize<<<1, 256>>>(g1, be1, NN, HC);

    // ---- layer 2 (BN1 affine + PReLU fused into A-load; head-mean fused into agg) ----
    gemm_tf32<<<gemmGrid, 256, GEMM_SMEM>>>(p_agg, W2, p_h, as2, ad2, NN,
                                            p_scale, p_shift, pw);
    agg_csr<<<aggBlocks, 256>>>(p_h, p_y, 1);
    bn_stats<<<512, 256>>>(p_y, NN, HID);
    bn_apply_elu<<<(NN * HID + 255) / 256, 256>>>(p_y, g2, be2, NN, HID);
    fc_out<<<(NN * OUTD + 255) / 256, 256>>>(fcW, fcb, out);
}